// round 7
// baseline (speedup 1.0000x reference)
#include <cuda_runtime.h>

// SNN forward scan: rows = B*N = 65536 independent length-512 recurrences.
// 64 rows per 64-thread block (grid 1024, ~1% SM imbalance). Smem-staged,
// 3-buffer depth-2 cp.async pipeline, fully coalesced 128B global traffic.
// R7: input loads carry L2::evict_first policy (zero-reuse stream; stop it
// evicting pending write lines), stores stay streaming (__stcs).
// Refractory window as multiplicative mask: ic = x*(1-s[t-1])*(1-s[t-2]).

#define T_STEPS 512
#define CHUNK   32
#define ROWS    64                // threads per block == rows per block
#define NCHUNK  (T_STEPS / CHUNK) // 16
#define STRIDE  36                // padded smem row stride (floats)
#define NBUF    3

__device__ __forceinline__ void cp_async16_ef(float* smem_dst, const float* gmem_src,
                                              unsigned long long pol) {
    unsigned saddr = (unsigned)__cvta_generic_to_shared(smem_dst);
    asm volatile("cp.async.cg.shared.global.L2::cache_hint [%0], [%1], 16, %2;\n"
                 :: "r"(saddr), "l"(gmem_src), "l"(pol));
}

__global__ __launch_bounds__(ROWS) void snn_fwd_kernel(
    const float* __restrict__ x,
    const float* __restrict__ beta,
    const float* __restrict__ p,
    const float* __restrict__ b,
    float* __restrict__ out,
    int N)
{
    __shared__ float tile[NBUF][ROWS * STRIDE];

    const int tid = threadIdx.x;
    const size_t row_base = (size_t)blockIdx.x * ROWS;
    const int n = (int)((row_base + tid) % (size_t)N);

    // L2 policy: input stream = evict_first (no reuse)
    unsigned long long pol;
    asm("createpolicy.fractional.L2::evict_first.b64 %0, 1.0;" : "=l"(pol));

    // clamped effective per-neuron params
    const float beta_c = fminf(fmaxf(beta[n], 0.001f), 0.999f);
    const float p_c    = fminf(fabsf(p[n]), 0.999f);
    const float b_c    = fminf(fmaxf(fabsf(b[n]), 0.001f), 1.0f);

    // recurrence state
    float mem = 0.0f, a = 0.0f, vth = 1.0f;
    float m1 = 1.0f, m2 = 1.0f;   // 1 - s(t-1), 1 - s(t-2)

    // cooperative addressing: g = k*ROWS + tid, g in [0, 512):
    // r = g>>3 (row), c4 = g&7 (16B slot); 8 consecutive threads cover
    // one row-chunk's 128 B -> fully coalesced lines.

    // preload chunks 0 and 1
    #pragma unroll
    for (int cc = 0; cc < 2; ++cc) {
        #pragma unroll
        for (int k = 0; k < 8; ++k) {
            const int g = k * ROWS + tid;
            const int r = g >> 3, c4 = g & 7;
            cp_async16_ef(&tile[cc][r * STRIDE + c4 * 4],
                          x + (row_base + r) * T_STEPS + cc * CHUNK + c4 * 4, pol);
        }
        asm volatile("cp.async.commit_group;\n");
    }

    for (int c = 0; c < NCHUNK; ++c) {
        const int buf = c % NBUF;

        if (c + 1 < NCHUNK) asm volatile("cp.async.wait_group 1;\n");
        else                asm volatile("cp.async.wait_group 0;\n");
        __syncthreads();   // chunk c visible; buffer (c+2)%NBUF free

        // prefetch chunk c+2
        if (c + 2 < NCHUNK) {
            const int buf2 = (c + 2) % NBUF;
            #pragma unroll
            for (int k = 0; k < 8; ++k) {
                const int g = k * ROWS + tid;
                const int r = g >> 3, c4 = g & 7;
                cp_async16_ef(&tile[buf2][r * STRIDE + c4 * 4],
                              x + (row_base + r) * T_STEPS + (c + 2) * CHUNK + c4 * 4,
                              pol);
            }
            asm volatile("cp.async.commit_group;\n");
        }

        // compute: each thread owns one smem row; overwrite x with spikes
        float* rowp = &tile[buf][tid * STRIDE];
        #pragma unroll
        for (int i = 0; i < CHUNK / 4; ++i) {
            float4 xv = *reinterpret_cast<float4*>(rowp + i * 4);
            float4 ov;
            #pragma unroll
            for (int k = 0; k < 4; ++k) {
                const float xt = (k == 0) ? xv.x : (k == 1) ? xv.y
                               : (k == 2) ? xv.z : xv.w;
                const float ic = xt * (m1 * m2);          // refractory mask
                const float nm = fmaf(mem, beta_c, ic);   // leaky integrate
                const float ns = (nm > vth) ? 0.0f : 1.0f;
                const float s  = 1.0f - ns;
                mem = nm * ns;                            // reset-to-zero
                a   = fmaf(p_c, a, s);                    // adaptation
                vth = fmaf(b_c, a, 1.0f);
                m2 = m1; m1 = ns;
                if (k == 0) ov.x = s; else if (k == 1) ov.y = s;
                else if (k == 2) ov.z = s; else ov.w = s;
            }
            *reinterpret_cast<float4*>(rowp + i * 4) = ov;
        }
        __syncthreads();   // spikes visible for cooperative store

        // cooperative coalesced streaming store
        #pragma unroll
        for (int k = 0; k < 8; ++k) {
            const int g = k * ROWS + tid;
            const int r = g >> 3, c4 = g & 7;
            const float4 v = *reinterpret_cast<const float4*>(
                &tile[buf][r * STRIDE + c4 * 4]);
            __stcs(reinterpret_cast<float4*>(
                out + (row_base + r) * T_STEPS + c * CHUNK + c4 * 4), v);
        }
        // buffer reuse gated by wait_group + __syncthreads at top of c+1
    }
}

extern "C" void kernel_launch(void* const* d_in, const int* in_sizes, int n_in,
                              void* d_out, int out_size)
{
    const float* x    = (const float*)d_in[0];
    const float* beta = (const float*)d_in[1];
    const float* p    = (const float*)d_in[2];
    const float* b    = (const float*)d_in[3];
    float* out        = (float*)d_out;

    const int N    = in_sizes[1];               // 1024
    const int rows = in_sizes[0] / T_STEPS;     // B*N = 65536

    const int blocks = rows / ROWS;             // 1024
    snn_fwd_kernel<<<blocks, ROWS>>>(x, beta, p, b, out, N);
}

// round 8
// speedup vs baseline: 1.0093x; 1.0093x over previous
#include <cuda_runtime.h>

// SNN forward scan: rows = B*N = 65536 independent length-512 recurrences.
// 64 rows per 64-thread block (grid 1024, ~1% SM imbalance). Smem-staged,
// 3-buffer depth-2 cp.async pipeline, fully coalesced 128B global traffic.
// R8: output stores use write-through (__stwt) so writes retire to DRAM
// inside the kernel window instead of as a deferred dirty-line burst that
// taxes the next graph replay.
// Refractory window as multiplicative mask: ic = x*(1-s[t-1])*(1-s[t-2]).

#define T_STEPS 512
#define CHUNK   32
#define ROWS    64                // threads per block == rows per block
#define NCHUNK  (T_STEPS / CHUNK) // 16
#define STRIDE  36                // padded smem row stride (floats)
#define NBUF    3

__device__ __forceinline__ void cp_async16(float* smem_dst, const float* gmem_src) {
    unsigned saddr = (unsigned)__cvta_generic_to_shared(smem_dst);
    asm volatile("cp.async.cg.shared.global [%0], [%1], 16;\n"
                 :: "r"(saddr), "l"(gmem_src));
}

__global__ __launch_bounds__(ROWS) void snn_fwd_kernel(
    const float* __restrict__ x,
    const float* __restrict__ beta,
    const float* __restrict__ p,
    const float* __restrict__ b,
    float* __restrict__ out,
    int N)
{
    __shared__ float tile[NBUF][ROWS * STRIDE];

    const int tid = threadIdx.x;
    const size_t row_base = (size_t)blockIdx.x * ROWS;
    const int n = (int)((row_base + tid) % (size_t)N);

    // clamped effective per-neuron params
    const float beta_c = fminf(fmaxf(beta[n], 0.001f), 0.999f);
    const float p_c    = fminf(fabsf(p[n]), 0.999f);
    const float b_c    = fminf(fmaxf(fabsf(b[n]), 0.001f), 1.0f);

    // recurrence state
    float mem = 0.0f, a = 0.0f, vth = 1.0f;
    float m1 = 1.0f, m2 = 1.0f;   // 1 - s(t-1), 1 - s(t-2)

    // cooperative addressing: g = k*ROWS + tid, g in [0, 512):
    // r = g>>3 (row), c4 = g&7 (16B slot); 8 consecutive threads cover
    // one row-chunk's 128 B -> fully coalesced lines.

    // preload chunks 0 and 1
    #pragma unroll
    for (int cc = 0; cc < 2; ++cc) {
        #pragma unroll
        for (int k = 0; k < 8; ++k) {
            const int g = k * ROWS + tid;
            const int r = g >> 3, c4 = g & 7;
            cp_async16(&tile[cc][r * STRIDE + c4 * 4],
                       x + (row_base + r) * T_STEPS + cc * CHUNK + c4 * 4);
        }
        asm volatile("cp.async.commit_group;\n");
    }

    for (int c = 0; c < NCHUNK; ++c) {
        const int buf = c % NBUF;

        if (c + 1 < NCHUNK) asm volatile("cp.async.wait_group 1;\n");
        else                asm volatile("cp.async.wait_group 0;\n");
        __syncthreads();   // chunk c visible; buffer (c+2)%NBUF free

        // prefetch chunk c+2
        if (c + 2 < NCHUNK) {
            const int buf2 = (c + 2) % NBUF;
            #pragma unroll
            for (int k = 0; k < 8; ++k) {
                const int g = k * ROWS + tid;
                const int r = g >> 3, c4 = g & 7;
                cp_async16(&tile[buf2][r * STRIDE + c4 * 4],
                           x + (row_base + r) * T_STEPS + (c + 2) * CHUNK + c4 * 4);
            }
            asm volatile("cp.async.commit_group;\n");
        }

        // compute: each thread owns one smem row; overwrite x with spikes
        float* rowp = &tile[buf][tid * STRIDE];
        #pragma unroll
        for (int i = 0; i < CHUNK / 4; ++i) {
            float4 xv = *reinterpret_cast<float4*>(rowp + i * 4);
            float4 ov;
            #pragma unroll
            for (int k = 0; k < 4; ++k) {
                const float xt = (k == 0) ? xv.x : (k == 1) ? xv.y
                               : (k == 2) ? xv.z : xv.w;
                const float ic = xt * (m1 * m2);          // refractory mask
                const float nm = fmaf(mem, beta_c, ic);   // leaky integrate
                const float ns = (nm > vth) ? 0.0f : 1.0f;
                const float s  = 1.0f - ns;
                mem = nm * ns;                            // reset-to-zero
                a   = fmaf(p_c, a, s);                    // adaptation
                vth = fmaf(b_c, a, 1.0f);
                m2 = m1; m1 = ns;
                if (k == 0) ov.x = s; else if (k == 1) ov.y = s;
                else if (k == 2) ov.z = s; else ov.w = s;
            }
            *reinterpret_cast<float4*>(rowp + i * 4) = ov;
        }
        __syncthreads();   // spikes visible for cooperative store

        // cooperative coalesced write-through store
        #pragma unroll
        for (int k = 0; k < 8; ++k) {
            const int g = k * ROWS + tid;
            const int r = g >> 3, c4 = g & 7;
            const float4 v = *reinterpret_cast<const float4*>(
                &tile[buf][r * STRIDE + c4 * 4]);
            __stwt(reinterpret_cast<float4*>(
                out + (row_base + r) * T_STEPS + c * CHUNK + c4 * 4), v);
        }
        // buffer reuse gated by wait_group + __syncthreads at top of c+1
    }
}

extern "C" void kernel_launch(void* const* d_in, const int* in_sizes, int n_in,
                              void* d_out, int out_size)
{
    const float* x    = (const float*)d_in[0];
    const float* beta = (const float*)d_in[1];
    const float* p    = (const float*)d_in[2];
    const float* b    = (const float*)d_in[3];
    float* out        = (float*)d_out;

    const int N    = in_sizes[1];               // 1024
    const int rows = in_sizes[0] / T_STEPS;     // B*N = 65536

    const int blocks = rows / ROWS;             // 1024
    snn_fwd_kernel<<<blocks, ROWS>>>(x, beta, p, b, out, N);
}

// round 9
// speedup vs baseline: 1.1346x; 1.1242x over previous
#include <cuda_runtime.h>

// SNN forward scan: rows = B*N = 65536 independent length-512 recurrences.
// R9: DRAM-page-locality variant. One warp per block, 32 rows. CHUNK=128
// timesteps -> every cooperative load/store iteration moves a full 512 B
// CONTIGUOUS run of one row (one DRAM page visit, 4x the contiguity of the
// 128B-comb pattern). Double-buffered cp.async, issue-then-wait. 4 pipeline
// iterations total. Refractory window as multiplicative mask:
// ic(t) = x(t) * (1-s(t-1)) * (1-s(t-2)).

#define T_STEPS 512
#define CHUNK   128
#define ROWS    32                // threads per block == rows per block
#define NCHUNK  (T_STEPS / CHUNK) // 4
#define STRIDE  132               // padded smem row stride (floats); 132%32=4 -> conflict-free
#define NBUF    2
#define LDI     32                // coop iterations per stage: ROWS*CHUNK/(32*4)

__device__ __forceinline__ void cp_async16(float* smem_dst, const float* gmem_src) {
    unsigned saddr = (unsigned)__cvta_generic_to_shared(smem_dst);
    asm volatile("cp.async.cg.shared.global [%0], [%1], 16;\n"
                 :: "r"(saddr), "l"(gmem_src));
}

__global__ __launch_bounds__(ROWS) void snn_fwd_kernel(
    const float* __restrict__ x,
    const float* __restrict__ beta,
    const float* __restrict__ p,
    const float* __restrict__ b,
    float* __restrict__ out,
    int N)
{
    __shared__ float tile[NBUF][ROWS * STRIDE];

    const int tid = threadIdx.x;
    const size_t row_base = (size_t)blockIdx.x * ROWS;
    const int n = (int)((row_base + tid) % (size_t)N);

    // clamped effective per-neuron params
    const float beta_c = fminf(fmaxf(beta[n], 0.001f), 0.999f);
    const float p_c    = fminf(fabsf(p[n]), 0.999f);
    const float b_c    = fminf(fmaxf(fabsf(b[n]), 0.001f), 1.0f);

    // recurrence state
    float mem = 0.0f, a = 0.0f, vth = 1.0f;
    float m1 = 1.0f, m2 = 1.0f;   // 1 - s(t-1), 1 - s(t-2)

    // cooperative addressing: iteration k moves row k's full 512B chunk;
    // the 32 lanes cover byte offsets tid*16 .. tid*16+15 -> one contiguous
    // 512B run per iteration (single-page DRAM burst).

    // preload chunk 0
    #pragma unroll
    for (int k = 0; k < LDI; ++k) {
        cp_async16(&tile[0][k * STRIDE + tid * 4],
                   x + (row_base + k) * T_STEPS + tid * 4);
    }
    asm volatile("cp.async.commit_group;\n");

    for (int c = 0; c < NCHUNK; ++c) {
        const int buf = c & 1;

        // issue next stage first (keeps a 16KB group in flight during wait)
        if (c + 1 < NCHUNK) {
            #pragma unroll
            for (int k = 0; k < LDI; ++k) {
                cp_async16(&tile[buf ^ 1][k * STRIDE + tid * 4],
                           x + (row_base + k) * T_STEPS + (c + 1) * CHUNK + tid * 4);
            }
            asm volatile("cp.async.commit_group;\n");
            asm volatile("cp.async.wait_group 1;\n");   // stage c arrived
        } else {
            asm volatile("cp.async.wait_group 0;\n");
        }
        __syncwarp();

        // compute: each thread owns one smem row; overwrite x with spikes
        float* rowp = &tile[buf][tid * STRIDE];
        #pragma unroll 8
        for (int i = 0; i < CHUNK / 4; ++i) {
            float4 xv = *reinterpret_cast<float4*>(rowp + i * 4);
            float4 ov;
            #pragma unroll
            for (int k = 0; k < 4; ++k) {
                const float xt = (k == 0) ? xv.x : (k == 1) ? xv.y
                               : (k == 2) ? xv.z : xv.w;
                const float ic = xt * (m1 * m2);          // refractory mask
                const float nm = fmaf(mem, beta_c, ic);   // leaky integrate
                const float ns = (nm > vth) ? 0.0f : 1.0f;
                const float s  = 1.0f - ns;
                mem = nm * ns;                            // reset-to-zero
                a   = fmaf(p_c, a, s);                    // adaptation
                vth = fmaf(b_c, a, 1.0f);
                m2 = m1; m1 = ns;
                if (k == 0) ov.x = s; else if (k == 1) ov.y = s;
                else if (k == 2) ov.z = s; else ov.w = s;
            }
            *reinterpret_cast<float4*>(rowp + i * 4) = ov;
        }
        __syncwarp();   // spikes visible warp-wide for cooperative store

        // cooperative store: one contiguous 512B run per iteration
        #pragma unroll
        for (int k = 0; k < LDI; ++k) {
            const float4 v = *reinterpret_cast<const float4*>(
                &tile[buf][k * STRIDE + tid * 4]);
            __stcs(reinterpret_cast<float4*>(
                out + (row_base + k) * T_STEPS + c * CHUNK + tid * 4), v);
        }
        // buffer reuse: stage c+2's prefetch (issued at top of c+1) targets
        // this buffer, and is program-ordered after this store loop.
    }
}

extern "C" void kernel_launch(void* const* d_in, const int* in_sizes, int n_in,
                              void* d_out, int out_size)
{
    const float* x    = (const float*)d_in[0];
    const float* beta = (const float*)d_in[1];
    const float* p    = (const float*)d_in[2];
    const float* b    = (const float*)d_in[3];
    float* out        = (float*)d_out;

    const int N    = in_sizes[1];               // 1024
    const int rows = in_sizes[0] / T_STEPS;     // B*N = 65536

    const int blocks = rows / ROWS;             // 2048
    snn_fwd_kernel<<<blocks, ROWS>>>(x, beta, p, b, out, N);
}